// round 2
// baseline (speedup 1.0000x reference)
#include <cuda_runtime.h>
#include <cstdint>

// Flip to 0 if the bench container runs pre-0.5 JAX (legacy threefry bits path).
#ifndef JAX_PARTITIONABLE
#define JAX_PARTITIONABLE 1
#endif

#define KIDS 64
#define NCANDS 16

__device__ unsigned long long g_pair[KIDS];   // (first << 32) | second
__device__ int g_count[KIDS];

__device__ __forceinline__ uint32_t rotl32(uint32_t v, int d) {
    return __funnelshift_l(v, v, d);
}

// JAX threefry2x32 (20 rounds), bit-exact.
__device__ __forceinline__ void tf2x32(uint32_t k0, uint32_t k1,
                                       uint32_t x0, uint32_t x1,
                                       uint32_t& o0, uint32_t& o1) {
    uint32_t k2 = k0 ^ k1 ^ 0x1BD11BDAu;
    x0 += k0; x1 += k1;
#define R_(r) { x0 += x1; x1 = rotl32(x1, (r)); x1 ^= x0; }
    R_(13) R_(15) R_(26) R_(6)   x0 += k1; x1 += k2 + 1u;
    R_(17) R_(29) R_(16) R_(24)  x0 += k2; x1 += k0 + 2u;
    R_(13) R_(15) R_(26) R_(6)   x0 += k0; x1 += k1 + 3u;
    R_(17) R_(29) R_(16) R_(24)  x0 += k1; x1 += k2 + 4u;
    R_(13) R_(15) R_(26) R_(6)   x0 += k2; x1 += k0 + 5u;
#undef R_
    o0 = x0; o1 = x1;
}

__global__ void init_kernel() {
    int t = threadIdx.x;
    if (t < KIDS) { g_pair[t] = 0x7FFFFFFF7FFFFFFFULL; g_count[t] = 0; }
}

// One pass over the mask: per-block (first, second, count) per id in smem,
// then 64-bit CAS two-smallest merge into globals.
__global__ void scan_kernel(const int* __restrict__ mask, int HW) {
    __shared__ int sF[KIDS], sS[KIDS], sC[KIDS];
    int t = threadIdx.x;
    if (t < KIDS) { sF[t] = 0x7FFFFFFF; sS[t] = 0x7FFFFFFF; sC[t] = 0; }
    __syncthreads();

    int base = (blockIdx.x * blockDim.x + t) * 4;
    int id0 = -1, id1 = -1, id2 = -1, id3 = -1;
    bool full = (base + 3 < HW);
    if (full) {
        int4 m = *reinterpret_cast<const int4*>(mask + base);
        id0 = m.x & (KIDS - 1); id1 = m.y & (KIDS - 1);
        id2 = m.z & (KIDS - 1); id3 = m.w & (KIDS - 1);
        atomicMin(&sF[id0], base);
        atomicMin(&sF[id1], base + 1);
        atomicMin(&sF[id2], base + 2);
        atomicMin(&sF[id3], base + 3);
        atomicAdd(&sC[id0], 1); atomicAdd(&sC[id1], 1);
        atomicAdd(&sC[id2], 1); atomicAdd(&sC[id3], 1);
    } else {
        for (int j = 0; j < 4; j++) {
            int idx = base + j;
            if (idx < HW) {
                int id = mask[idx] & (KIDS - 1);
                atomicMin(&sF[id], idx);
                atomicAdd(&sC[id], 1);
            }
        }
    }
    __syncthreads();
    if (full) {
        if (base     != sF[id0]) atomicMin(&sS[id0], base);
        if (base + 1 != sF[id1]) atomicMin(&sS[id1], base + 1);
        if (base + 2 != sF[id2]) atomicMin(&sS[id2], base + 2);
        if (base + 3 != sF[id3]) atomicMin(&sS[id3], base + 3);
    } else {
        for (int j = 0; j < 4; j++) {
            int idx = base + j;
            if (idx < HW) {
                int id = mask[idx] & (KIDS - 1);
                if (idx != sF[id]) atomicMin(&sS[id], idx);
            }
        }
    }
    __syncthreads();

    if (t < KIDS && sC[t] > 0) {
        atomicAdd(&g_count[t], sC[t]);
        unsigned f2 = (unsigned)sF[t], s2 = (unsigned)sS[t];
        unsigned long long old = g_pair[t];
        while (true) {
            unsigned f1 = (unsigned)(old >> 32), s1 = (unsigned)old;
            unsigned nf = min(f1, f2);
            unsigned ns = min(max(f1, f2), min(s1, s2));
            unsigned long long nv = ((unsigned long long)nf << 32) | ns;
            if (nv == old) break;
            unsigned long long prev = atomicCAS(&g_pair[t], old, nv);
            if (prev == old) break;
            old = prev;
        }
    }
}

// One block: RNG negatives (bit-exact JAX threefry), gathers, triplet loss, final scalar.
__global__ void finalize_kernel(const float* __restrict__ sem,
                                const int* __restrict__ mask,
                                float* __restrict__ out, int HW, int BC) {
    __shared__ float sPer[KIDS];
    __shared__ int   sVal[KIDS];
    int t = threadIdx.x, warp = t >> 5, lane = t & 31;
    int nw = blockDim.x >> 5;

    // child key k2 of split(key(1)) = split((0,1))
    uint32_t kk0, kk1;
#if JAX_PARTITIONABLE
    tf2x32(0u, 1u, 0u, 1u, kk0, kk1);
#else
    { uint32_t a0, b0, a1, b1;
      tf2x32(0u, 1u, 0u, 2u, a0, b0);
      tf2x32(0u, 1u, 1u, 3u, a1, b1);
      kk0 = b0; kk1 = b1; }
#endif

    for (int k = warp; k < KIDS; k += nw) {
        unsigned long long pair = g_pair[k];
        int cnt = g_count[k];
        int f = (int)min((unsigned)(pair >> 32), (unsigned)(HW - 1));
        int s = (int)min((unsigned)pair, (unsigned)(HW - 1));

        // random negative: first of 16 candidates whose mask id differs
        int cand = 0; bool ok = false;
        if (lane < NCANDS) {
            int idx = k * NCANDS + lane;
            uint32_t o0, o1;
#if JAX_PARTITIONABLE
            tf2x32(kk0, kk1, 0u, (uint32_t)idx, o0, o1);
            cand = (int)((o0 ^ o1) % (uint32_t)HW);
#else
            const int half = (KIDS * NCANDS) / 2;
            if (idx < half) { tf2x32(kk0, kk1, (uint32_t)idx, (uint32_t)(idx + half), o0, o1);
                              cand = (int)(o0 % (uint32_t)HW); }
            else            { tf2x32(kk0, kk1, (uint32_t)(idx - half), (uint32_t)idx, o0, o1);
                              cand = (int)(o1 % (uint32_t)HW); }
#endif
            ok = (mask[cand] != k);
        }
        unsigned bal = __ballot_sync(0xffffffffu, ok);
        int pick = bal ? (__ffs(bal) - 1) : 0;
        int neg = __shfl_sync(0xffffffffu, cand, pick);

        // pairwise distances over BC channels, lanes parallel over channels
        float dap = 0.f, dan = 0.f;
        for (int c = lane; c < BC; c += 32) {
            const float* b = sem + (size_t)c * (size_t)HW;
            float av = __ldg(b + f);
            float pv = __ldg(b + s);
            float nv2 = __ldg(b + neg);
            float d1 = av - pv + 1e-6f;
            float d2 = av - nv2 + 1e-6f;
            dap = fmaf(d1, d1, dap);
            dan = fmaf(d2, d2, dan);
        }
        #pragma unroll
        for (int o = 16; o; o >>= 1) {
            dap += __shfl_down_sync(0xffffffffu, dap, o);
            dan += __shfl_down_sync(0xffffffffu, dan, o);
        }
        if (lane == 0) {
            bool valid = (cnt >= 2) && (k != 0);
            float per = fmaxf(sqrtf(dap) - sqrtf(dan) + 1.0f, 0.0f);
            sPer[k] = valid ? per : 0.0f;
            sVal[k] = valid ? 1 : 0;
        }
    }
    __syncthreads();
    if (t == 0) {  // deterministic serial reduction over 64 ids
        float tot = 0.f; int c = 0;
        for (int k = 0; k < KIDS; k++) { tot += sPer[k]; c += sVal[k]; }
        out[0] = (c > 0) ? tot / (float)c : 0.0f;
    }
}

extern "C" void kernel_launch(void* const* d_in, const int* in_sizes, int n_in,
                              void* d_out, int out_size) {
    const float* sem  = (const float*)d_in[0];
    const int*   mask = (const int*)d_in[1];
    float*       out  = (float*)d_out;
    int HW = in_sizes[1];
    int BC = in_sizes[0] / HW;

    init_kernel<<<1, KIDS>>>();
    int threads = 256;
    int per_block = threads * 4;
    int blocks = (HW + per_block - 1) / per_block;
    scan_kernel<<<blocks, threads>>>(mask, HW);
    finalize_kernel<<<1, 1024>>>(sem, mask, out, HW, BC);
}